// round 14
// baseline (speedup 1.0000x reference)
#include <cuda_runtime.h>
#include <cuda_bf16.h>
#include <cstdint>
#include <cstddef>

#define N_NODES 100000
#define N_EDGES 1600000
#define EDGE_TILES 10   // 128-edge tiles per CTA -> 1250 CTAs (128 threads each)
#define NODE_TILES 1    // 128-node tiles per CTA -> 782 CTAs (256 threads)

// ---------------------------------------------------------------------------
// Device scratch
// ---------------------------------------------------------------------------
__device__ float g_agg[(size_t)N_NODES * 32];
// Fragment-order weight images: per (mat, kt, j, lane) a uint4 {bh0,bh1,bl0,bl1}
// eW1: uint4[   0..1535]  (6 kt x 8 j x 32 lanes)
// eW2: uint4[1536..2559]  (4 x 8 x 32)
// eW3: uint4[2560..3071]  (4 x 4 x 32)
// nW1: uint4[3072..4095], nW2: [4096..5119], nW3: [5120..5631]
__device__ __align__(16) uint4 g_wfrag[5632];

// ---------------------------------------------------------------------------
// Helpers
// ---------------------------------------------------------------------------
__device__ __forceinline__ uint32_t split2(float x0, float x1, uint32_t& lo) {
    uint32_t hw;
    asm("cvt.rn.bf16x2.f32 %0, %1, %2;" : "=r"(hw) : "f"(x1), "f"(x0));
    float h0 = __uint_as_float(hw << 16);
    float h1 = __uint_as_float(hw & 0xffff0000u);
    asm("cvt.rn.bf16x2.f32 %0, %1, %2;" : "=r"(lo) : "f"(x1 - h1), "f"(x0 - h0));
    return hw;
}

__device__ __forceinline__ void mma16816(float c[4], const uint32_t a[4],
                                         uint32_t b0, uint32_t b1) {
    asm("mma.sync.aligned.m16n8k16.row.col.f32.bf16.bf16.f32 "
        "{%0,%1,%2,%3},{%4,%5,%6,%7},{%8,%9},{%0,%1,%2,%3};"
        : "+f"(c[0]), "+f"(c[1]), "+f"(c[2]), "+f"(c[3])
        : "r"(a[0]), "r"(a[1]), "r"(a[2]), "r"(a[3]), "r"(b0), "r"(b1));
}

// Dual-j, dual-subtile split-3 block: 2 B-fragment LDS.128 feed 12 HMMA with
// same-accumulator dependency distance 4.
__device__ __forceinline__ void mma3x4(float c0a[4], float c0b[4],
                                       float c1a[4], float c1b[4],
                                       const uint32_t ahA[4], const uint32_t alA[4],
                                       const uint32_t ahB[4], const uint32_t alB[4],
                                       const uint4* f0, const uint4* f1) {
    uint4 b0 = *f0, b1 = *f1;
    mma16816(c0a, ahA, b0.x, b0.y);
    mma16816(c0b, ahB, b0.x, b0.y);
    mma16816(c1a, ahA, b1.x, b1.y);
    mma16816(c1b, ahB, b1.x, b1.y);
    mma16816(c0a, ahA, b0.z, b0.w);
    mma16816(c0b, ahB, b0.z, b0.w);
    mma16816(c1a, ahA, b1.z, b1.w);
    mma16816(c1b, ahB, b1.z, b1.w);
    mma16816(c0a, alA, b0.x, b0.y);
    mma16816(c0b, alB, b0.x, b0.y);
    mma16816(c1a, alA, b1.x, b1.y);
    mma16816(c1b, alB, b1.x, b1.y);
}

// single-tile variant (node kernel)
__device__ __forceinline__ void mma3f(float c[4], const uint32_t ah[4], const uint32_t al[4],
                                      const uint4* f) {
    uint4 b = *f;
    mma16816(c, ah, b.x, b.y);
    mma16816(c, ah, b.z, b.w);
    mma16816(c, al, b.x, b.y);
}

__device__ __forceinline__ void red4(float* p, float4 v) {
    asm volatile("red.global.add.v4.f32 [%0], {%1,%2,%3,%4};"
                 :: "l"(p), "f"(v.x), "f"(v.y), "f"(v.z), "f"(v.w) : "memory");
}

__device__ __forceinline__ void pf_l1(const void* p) {
    asm volatile("prefetch.global.L1 [%0];" :: "l"(p));
}

// bias + relu + split c[8][4] (N=64) -> next-layer A fragments (4 k-tiles)
__device__ __forceinline__ void convert(const float c[8][4], const float* bias, int cc,
                                        uint32_t ah[4][4], uint32_t al[4][4]) {
    #pragma unroll
    for (int kk = 0; kk < 4; kk++) {
        #pragma unroll
        for (int h = 0; h < 2; h++) {
            int j = 2 * kk + h;
            float2 bb = *(const float2*)(bias + 8 * j + 2 * cc);
            float x0 = fmaxf(c[j][0] + bb.x, 0.f);
            float x1 = fmaxf(c[j][1] + bb.y, 0.f);
            float x2 = fmaxf(c[j][2] + bb.x, 0.f);
            float x3 = fmaxf(c[j][3] + bb.y, 0.f);
            ah[kk][2 * h]     = split2(x0, x1, al[kk][2 * h]);
            ah[kk][2 * h + 1] = split2(x2, x3, al[kk][2 * h + 1]);
        }
    }
}

// ---------------------------------------------------------------------------
// Prep: fragment-order hi/lo bf16 weight images. One uint4 per thread.
// ---------------------------------------------------------------------------
__global__ void prep_weights(const float* __restrict__ eW1, const float* __restrict__ eW2,
                             const float* __restrict__ eW3, const float* __restrict__ nW1,
                             const float* __restrict__ nW2, const float* __restrict__ nW3) {
    int id = blockIdx.x * blockDim.x + threadIdx.x;
    if (id >= 5632) return;
    const float* W; int NJ, N; int rel;
    if      (id < 1536) { W = eW1; NJ = 8; N = 64; rel = id; }
    else if (id < 2560) { W = eW2; NJ = 8; N = 64; rel = id - 1536; }
    else if (id < 3072) { W = eW3; NJ = 4; N = 32; rel = id - 2560; }
    else if (id < 4096) { W = nW1; NJ = 8; N = 64; rel = id - 3072; }
    else if (id < 5120) { W = nW2; NJ = 8; N = 64; rel = id - 4096; }
    else                { W = nW3; NJ = 4; N = 32; rel = id - 5120; }
    int lane = rel & 31, fi = rel >> 5;
    int kt = fi / NJ, j = fi % NJ;
    int n = 8 * j + (lane >> 2);
    int k0 = kt * 16 + 2 * (lane & 3);
    float x0 = W[(size_t)k0 * N + n];
    float x1 = W[(size_t)(k0 + 1) * N + n];
    float x2 = W[(size_t)(k0 + 8) * N + n];
    float x3 = W[(size_t)(k0 + 9) * N + n];
    uint4 o;
    o.x = split2(x0, x1, o.z);
    o.y = split2(x2, x3, o.w);
    g_wfrag[id] = o;
}

__global__ void zero_agg_kernel() {
    int i = blockIdx.x * blockDim.x + threadIdx.x;
    reinterpret_cast<float4*>(g_agg)[i] = make_float4(0.f, 0.f, 0.f, 0.f);
}

// ---------------------------------------------------------------------------
// Edge kernel: 128 threads = 4 warps, M=32 edges/warp (two m16 subtiles
// sharing every B-fragment load), EDGE_TILES tiles per CTA. occ 3.
// Next-tile row prefetch into L1 covers the gather chain at tile boundaries.
// SMEM: 3072 uint4 weight frags (49152 B) + 160 bias + 4 warp bufs.
// ---------------------------------------------------------------------------
#define EDGE_WU4  3072
#define EDGE_SMEM (49152 + 640 + 4 * 2304)

__global__ void __launch_bounds__(128, 3)
edge_kernel(const float* __restrict__ nf, const float* __restrict__ ef,
            const int* __restrict__ src, const int* __restrict__ dst,
            const float* __restrict__ b1, const float* __restrict__ b2,
            const float* __restrict__ b3, float* __restrict__ out_ef) {
    extern __shared__ char sm[];
    const int tid = threadIdx.x, wid = tid >> 5, lane = tid & 31;

    uint4* wf = (uint4*)sm;
    for (int i = tid; i < EDGE_WU4; i += 128) wf[i] = g_wfrag[i];
    float* bias = (float*)(sm + 49152);
    if (tid < 64)       bias[tid] = b1[tid];
    else if (tid < 128) bias[tid] = b2[tid - 64];
    if (tid < 32)       bias[128 + tid] = b3[tid];
    float* buf = (float*)(sm + 49792) + wid * 576;
    __syncthreads();

    const int r = lane >> 2, cc = lane & 3;
    const uint4* F1 = wf;            // 6 kt x 8 j x 32
    const uint4* F2 = wf + 1536;     // 4 x 8 x 32
    const uint4* F3 = wf + 2560;     // 4 x 4 x 32

    for (int t = 0; t < EDGE_TILES; t++) {
        const int ew = (blockIdx.x * EDGE_TILES + t) * 128 + wid * 32;
        const int eA0 = ew + r,       eA1 = ew + 8 + r;
        const int eB0 = ew + 16 + r,  eB1 = ew + 24 + r;
        const int sA0 = src[eA0], sA1 = src[eA1], sB0 = src[eB0], sB1 = src[eB1];
        const int dA0 = dst[eA0], dA1 = dst[eA1], dB0 = dst[eB0], dB1 = dst[eB1];

        // ---- next-tile index loads (transient) for L1 row prefetch ----
        const bool hasNext = (t + 1 < EDGE_TILES);
        const int en = ew + 128;
        int psA0 = 0, psA1 = 0, psB0 = 0, psB1 = 0;
        int pdA0 = 0, pdA1 = 0, pdB0 = 0, pdB1 = 0;
        if (hasNext) {
            psA0 = src[en + r];      psA1 = src[en + 8 + r];
            psB0 = src[en + 16 + r]; psB1 = src[en + 24 + r];
            pdA0 = dst[en + r];      pdA1 = dst[en + 8 + r];
            pdB0 = dst[en + 16 + r]; pdB1 = dst[en + 24 + r];
        }

        float cA[8][4], cB[8][4];
        #pragma unroll
        for (int j = 0; j < 8; j++)
            #pragma unroll
            for (int q = 0; q < 4; q++) { cA[j][q] = 0.f; cB[j][q] = 0.f; }

        // ---- L1: K = 96, A fragments gathered straight from global ----
        #pragma unroll
        for (int kt = 0; kt < 6; kt++) {
            const int cls = kt >> 1;
            const float *pA0, *pA1, *pB0, *pB1;
            if (cls == 0) {
                pA0 = nf + (size_t)sA0 * 32; pA1 = nf + (size_t)sA1 * 32;
                pB0 = nf + (size_t)sB0 * 32; pB1 = nf + (size_t)sB1 * 32;
            } else if (cls == 1) {
                pA0 = nf + (size_t)dA0 * 32; pA1 = nf + (size_t)dA1 * 32;
                pB0 = nf + (size_t)dB0 * 32; pB1 = nf + (size_t)dB1 * 32;
            } else {
                pA0 = ef + (size_t)eA0 * 32; pA1 = ef + (size_t)eA1 * 32;
                pB0 = ef + (size_t)eB0 * 32; pB1 = ef + (size_t)eB1 * 32;
            }
            const int o = ((kt & 1) << 4) + 2 * cc;
            float2 a00 = *(const float2*)(pA0 + o), a01 = *(const float2*)(pA0 + o + 8);
            float2 a10 = *(const float2*)(pA1 + o), a11 = *(const float2*)(pA1 + o + 8);
            float2 b00 = *(const float2*)(pB0 + o), b01 = *(const float2*)(pB0 + o + 8);
            float2 b10 = *(const float2*)(pB1 + o), b11 = *(const float2*)(pB1 + o + 8);
            uint32_t ahA[4], alA[4], ahB[4], alB[4];
            ahA[0] = split2(a00.x, a00.y, alA[0]);
            ahA[1] = split2(a10.x, a10.y, alA[1]);
            ahA[2] = split2(a01.x, a01.y, alA[2]);
            ahA[3] = split2(a11.x, a11.y, alA[3]);
            ahB[0] = split2(b00.x, b00.y, alB[0]);
            ahB[1] = split2(b10.x, b10.y, alB[1]);
            ahB[2] = split2(b01.x, b01.y, alB[2]);
            ahB[3] = split2(b11.x, b11.y, alB[3]);
            const uint4* fp = F1 + kt * 256 + lane;
            #pragma unroll
            for (int jj = 0; jj < 4; jj++)
                mma3x4(cA[2 * jj], cB[2 * jj], cA[2 * jj + 1], cB[2 * jj + 1],
                       ahA, alA, ahB, alB, fp + (2 * jj) * 32, fp + (2 * jj + 1) * 32);
        }

        // ---- prefetch next tile's rows into L1 (indices now dead after this) ----
        if (hasNext) {
            pf_l1(nf + (size_t)psA0 * 32); pf_l1(nf + (size_t)psA1 * 32);
            pf_l1(nf + (size_t)psB0 * 32); pf_l1(nf + (size_t)psB1 * 32);
            pf_l1(nf + (size_t)pdA0 * 32); pf_l1(nf + (size_t)pdA1 * 32);
            pf_l1(nf + (size_t)pdB0 * 32); pf_l1(nf + (size_t)pdB1 * 32);
            pf_l1(ef + (size_t)(en + r) * 32);
            pf_l1(ef + (size_t)(en + 8 + r) * 32);
            pf_l1(ef + (size_t)(en + 16 + r) * 32);
            pf_l1(ef + (size_t)(en + 24 + r) * 32);
        }

        uint32_t a2hA[4][4], a2lA[4][4], a2hB[4][4], a2lB[4][4];
        convert(cA, bias, cc, a2hA, a2lA);
        convert(cB, bias, cc, a2hB, a2lB);

        // ---- L2: K = 64 ----
        #pragma unroll
        for (int j = 0; j < 8; j++)
            #pragma unroll
            for (int q = 0; q < 4; q++) { cA[j][q] = 0.f; cB[j][q] = 0.f; }
        #pragma unroll
        for (int kt = 0; kt < 4; kt++) {
            const uint4* fp = F2 + kt * 256 + lane;
            #pragma unroll
            for (int jj = 0; jj < 4; jj++)
                mma3x4(cA[2 * jj], cB[2 * jj], cA[2 * jj + 1], cB[2 * jj + 1],
                       a2hA[kt], a2lA[kt], a2hB[kt], a2lB[kt],
                       fp + (2 * jj) * 32, fp + (2 * jj + 1) * 32);
        }

        convert(cA, bias + 64, cc, a2hA, a2lA);   // reuse as a3
        convert(cB, bias + 64, cc, a2hB, a2lB);

        // ---- L3: K = 64, N = 32 (reuse cA/cB rows 0..3) ----
        #pragma unroll
        for (int j = 0; j < 4; j++)
            #pragma unroll
            for (int q = 0; q < 4; q++) { cA[j][q] = 0.f; cB[j][q] = 0.f; }
        #pragma unroll
        for (int kt = 0; kt < 4; kt++) {
            const uint4* fp = F3 + kt * 128 + lane;
            #pragma unroll
            for (int jj = 0; jj < 2; jj++)
                mma3x4(cA[2 * jj], cB[2 * jj], cA[2 * jj + 1], cB[2 * jj + 1],
                       a2hA[kt], a2lA[kt], a2hB[kt], a2lB[kt],
                       fp + (2 * jj) * 32, fp + (2 * jj + 1) * 32);
        }

        // ---- epilogue, half A then half B through the 16-row warp buf ----
        #pragma unroll
        for (int half = 0; half < 2; half++) {
            #pragma unroll
            for (int j = 0; j < 4; j++) {
                float2 bb = *(const float2*)(bias + 128 + 8 * j + 2 * cc);
                int col = 8 * j + 2 * cc;
                const float* cj = half ? cB[j] : cA[j];
                buf[r * 36 + col]           = fmaxf(cj[0] + bb.x, 0.f);
                buf[r * 36 + col + 1]       = fmaxf(cj[1] + bb.y, 0.f);
                buf[(r + 8) * 36 + col]     = fmaxf(cj[2] + bb.x, 0.f);
                buf[(r + 8) * 36 + col + 1] = fmaxf(cj[3] + bb.y, 0.f);
            }
            __syncwarp();
            {
                const int row = lane >> 1, hh = lane & 1;
                const int e_row = ew + half * 16 + row;
                const int d = dst[e_row];
                const float* bp = buf + row * 36 + hh * 16;
                float4 v0 = *(const float4*)(bp);
                float4 v1 = *(const float4*)(bp + 4);
                float4 v2 = *(const float4*)(bp + 8);
                float4 v3 = *(const float4*)(bp + 12);
                float4* op = (float4*)(out_ef + (size_t)e_row * 32 + hh * 16);
                op[0] = v0; op[1] = v1; op[2] = v2; op[3] = v3;
                float* ap = g_agg + (size_t)d * 32 + hh * 16;
                red4(ap, v0); red4(ap + 4, v1); red4(ap + 8, v2); red4(ap + 12, v3);
            }
            __syncwarp();
        }
    }
}

// ---------------------------------------------------------------------------
// Node kernel: 256 threads, NODE_TILES x 128 nodes per CTA.
// NODE_TILES=1 -> 782 CTAs: finer wave granularity (was 1.32 waves @ 391).
// ---------------------------------------------------------------------------
#define NODE_WU4  2560
#define NODE_SMEM (40960 + 640 + 8 * 2304)

__global__ void __launch_bounds__(256, 2)
node_kernel(const float* __restrict__ nf,
            const float* __restrict__ b1, const float* __restrict__ b2,
            const float* __restrict__ b3, float* __restrict__ out_nf) {
    extern __shared__ char sm[];
    const int tid = threadIdx.x, wid = tid >> 5, lane = tid & 31;

    uint4* wf = (uint4*)sm;
    for (int i = tid; i < NODE_WU4; i += 256) wf[i] = g_wfrag[3072 + i];
    float* bias = (float*)(sm + 40960);
    if (tid < 64)       bias[tid] = b1[tid];
    else if (tid < 128) bias[tid] = b2[tid - 64];
    else if (tid < 160) bias[tid] = b3[tid - 128];
    float* buf = (float*)(sm + 41600) + wid * 576;
    __syncthreads();

    const int r = lane >> 2, cc = lane & 3;
    const uint4* F1 = wf;
    const uint4* F2 = wf + 1024;
    const uint4* F3 = wf + 2048;

    for (int t = 0; t < NODE_TILES; t++) {
        const int n0w = (blockIdx.x * NODE_TILES + t) * 128 + wid * 16;
        if (n0w >= N_NODES) break;
        const int ra = min(n0w + r, N_NODES - 1);
        const int rb = min(n0w + r + 8, N_NODES - 1);
        const float* PA[2] = { nf + (size_t)ra * 32, g_agg + (size_t)ra * 32 };
        const float* PB[2] = { nf + (size_t)rb * 32, g_agg + (size_t)rb * 32 };

        float c[8][4];
        #pragma unroll
        for (int j = 0; j < 8; j++) { c[j][0] = c[j][1] = c[j][2] = c[j][3] = 0.f; }

        #pragma unroll
        for (int kt = 0; kt < 4; kt++) {
            const float* pa = PA[kt >> 1];
            const float* pb = PB[kt >> 1];
            const int o = ((kt & 1) << 4) + 2 * cc;
            float2 va0 = *(const float2*)(pa + o), va1 = *(const float2*)(pa + o + 8);
            float2 vb0 = *(const float2*)(pb + o), vb1 = *(const float2*)(pb + o + 8);
            uint32_t ah[4], al[4];
            ah[0] = split2(va0.x, va0.y, al[0]);
            ah[1] = split2(vb0.x, vb0.y, al[1]);
            ah[2] = split2(va1.x, va1.y, al[2]);
            ah[3] = split2(vb1.x, vb1.y, al[3]);
            const uint4* fp = F1 + kt * 256 + lane;
            #pragma unroll
            for (int j = 0; j < 8; j++)
                mma3f(c[j], ah, al, fp + j * 32);
        }

        uint32_t a2h[4][4], a2l[4][4];
        convert(c, bias, cc, a2h, a2l);

        #pragma unroll
        for (int j = 0; j < 8; j++) { c[j][0] = c[j][1] = c[j][2] = c[j][3] = 0.f; }
        #pragma unroll
        for (int kt = 0; kt < 4; kt++) {
            const uint4* fp = F2 + kt * 256 + lane;
            #pragma unroll
            for (int j = 0; j < 8; j++)
                mma3f(c[j], a2h[kt], a2l[kt], fp + j * 32);
        }

        convert(c, bias + 64, cc, a2h, a2l);   // reuse as a3

        float c3[4][4];
        #pragma unroll
        for (int j = 0; j < 4; j++) { c3[j][0] = c3[j][1] = c3[j][2] = c3[j][3] = 0.f; }
        #pragma unroll
        for (int kt = 0; kt < 4; kt++) {
            const uint4* fp = F3 + kt * 128 + lane;
            #pragma unroll
            for (int j = 0; j < 4; j++)
                mma3f(c3[j], a2h[kt], a2l[kt], fp + j * 32);
        }

        #pragma unroll
        for (int j = 0; j < 4; j++) {
            float2 bb = *(const float2*)(bias + 128 + 8 * j + 2 * cc);
            int col = 8 * j + 2 * cc;
            buf[r * 36 + col]           = fmaxf(c3[j][0] + bb.x, 0.f);
            buf[r * 36 + col + 1]       = fmaxf(c3[j][1] + bb.y, 0.f);
            buf[(r + 8) * 36 + col]     = fmaxf(c3[j][2] + bb.x, 0.f);
            buf[(r + 8) * 36 + col + 1] = fmaxf(c3[j][3] + bb.y, 0.f);
        }
        __syncwarp();
        {
            const int row = lane >> 1, half = lane & 1;
            const int n_row = n0w + row;
            if (n_row < N_NODES) {
                const float* bp = buf + row * 36 + half * 16;
                float4* op = (float4*)(out_nf + (size_t)n_row * 32 + half * 16);
                op[0] = *(const float4*)(bp);
                op[1] = *(const float4*)(bp + 4);
                op[2] = *(const float4*)(bp + 8);
                op[3] = *(const float4*)(bp + 12);
            }
        }
        __syncwarp();
    }
}

// ---------------------------------------------------------------------------
extern "C" void kernel_launch(void* const* d_in, const int* in_sizes, int n_in,
                              void* d_out, int out_size) {
    const float* nf  = (const float*)d_in[0];
    const float* ef  = (const float*)d_in[1];
    const int*   src = (const int*)d_in[2];
    const int*   dst = (const int*)d_in[3];
    const float* eW1 = (const float*)d_in[4];
    const float* eb1 = (const float*)d_in[5];
    const float* eW2 = (const float*)d_in[6];
    const float* eb2 = (const float*)d_in[7];
    const float* eW3 = (const float*)d_in[8];
    const float* eb3 = (const float*)d_in[9];
    const float* nW1 = (const float*)d_in[10];
    const float* nb1 = (const float*)d_in[11];
    const float* nW2 = (const float*)d_in[12];
    const float* nb2 = (const float*)d_in[13];
    const float* nW3 = (const float*)d_in[14];
    const float* nb3 = (const float*)d_in[15];

    float* out_nf = (float*)d_out;
    float* out_ef = out_nf + (size_t)N_NODES * 32;

    cudaFuncSetAttribute(edge_kernel, cudaFuncAttributeMaxDynamicSharedMemorySize, EDGE_SMEM);
    cudaFuncSetAttribute(node_kernel, cudaFuncAttributeMaxDynamicSharedMemorySize, NODE_SMEM);

    prep_weights<<<44, 128>>>(eW1, eW2, eW3, nW1, nW2, nW3);
    zero_agg_kernel<<<3125, 256>>>();
    edge_kernel<<<N_EDGES / (128 * EDGE_TILES), 128, EDGE_SMEM>>>(
        nf, ef, src, dst, eb1, eb2, eb3, out_ef);
    node_kernel<<<(N_NODES + 127) / 128, 256, NODE_SMEM>>>(
        nf, nb1, nb2, nb3, out_nf);
}

// round 17
// speedup vs baseline: 1.3006x; 1.3006x over previous
#include <cuda_runtime.h>
#include <cuda_fp16.h>
#include <cstdint>
#include <cstddef>

#define N_NODES 100000
#define N_EDGES 1600000
#define EDGE_TILES 10   // 128-edge tiles per CTA -> 1250 CTAs (128 threads each)
#define NODE_TILES 2    // 128-node tiles per CTA -> 391 CTAs (256 threads)

// ---------------------------------------------------------------------------
// Device scratch
// ---------------------------------------------------------------------------
__device__ float g_agg[(size_t)N_NODES * 32];
// Fragment-order fp16 weight images: per (mat, kt, jpair, lane) a uint4
// {b0(j0), b1(j0), b0(j1), b1(j1)} — one LDS.128 feeds 8 HMMA (2 j x 2 products).
// eW1: uint4[   0.. 767]  (6 kt x 4 jp x 32 lanes)
// eW2: uint4[ 768..1279]  (4 x 4 x 32)
// eW3: uint4[1280..1535]  (4 x 2 x 32)
// nW1: uint4[1536..2047], nW2: [2048..2559], nW3: [2560..2815]
__device__ __align__(16) uint4 g_wfrag[2816];

// ---------------------------------------------------------------------------
// Helpers
// ---------------------------------------------------------------------------
__device__ __forceinline__ uint32_t packh(float x0, float x1) {
    uint32_t h;
    asm("cvt.rn.f16x2.f32 %0, %1, %2;" : "=r"(h) : "f"(x1), "f"(x0));
    return h;
}

// exact fp16 split: x = h + l with h = f16(x), l = f16(x - h)
__device__ __forceinline__ uint32_t split2h(float x0, float x1, uint32_t& lo) {
    uint32_t hw;
    asm("cvt.rn.f16x2.f32 %0, %1, %2;" : "=r"(hw) : "f"(x1), "f"(x0));
    __half2 hh = *reinterpret_cast<__half2*>(&hw);
    float h0 = __low2float(hh);
    float h1 = __high2float(hh);
    asm("cvt.rn.f16x2.f32 %0, %1, %2;" : "=r"(lo) : "f"(x1 - h1), "f"(x0 - h0));
    return hw;
}

__device__ __forceinline__ void mmah(float c[4], const uint32_t a[4],
                                     uint32_t b0, uint32_t b1) {
    asm("mma.sync.aligned.m16n8k16.row.col.f32.f16.f16.f32 "
        "{%0,%1,%2,%3},{%4,%5,%6,%7},{%8,%9},{%0,%1,%2,%3};"
        : "+f"(c[0]), "+f"(c[1]), "+f"(c[2]), "+f"(c[3])
        : "r"(a[0]), "r"(a[1]), "r"(a[2]), "r"(a[3]), "r"(b0), "r"(b1));
}

// Edge: one uint4 B-load feeds 8 HMMA (2 j-tiles x {Ah,Al} x 2 subtiles).
__device__ __forceinline__ void mma2x4(float c0a[4], float c0b[4],
                                       float c1a[4], float c1b[4],
                                       const uint32_t ahA[4], const uint32_t alA[4],
                                       const uint32_t ahB[4], const uint32_t alB[4],
                                       const uint4* f) {
    uint4 b = *f;
    mmah(c0a, ahA, b.x, b.y);
    mmah(c0b, ahB, b.x, b.y);
    mmah(c1a, ahA, b.z, b.w);
    mmah(c1b, ahB, b.z, b.w);
    mmah(c0a, alA, b.x, b.y);
    mmah(c0b, alB, b.x, b.y);
    mmah(c1a, alA, b.z, b.w);
    mmah(c1b, alB, b.z, b.w);
}

// Node: one uint4 B-load feeds 4 HMMA (2 j-tiles x {Ah,Al}).
__device__ __forceinline__ void mma2x2(float c0[4], float c1[4],
                                       const uint32_t ah[4], const uint32_t al[4],
                                       const uint4* f) {
    uint4 b = *f;
    mmah(c0, ah, b.x, b.y);
    mmah(c1, ah, b.z, b.w);
    mmah(c0, al, b.x, b.y);
    mmah(c1, al, b.z, b.w);
}

__device__ __forceinline__ void red4(float* p, float4 v) {
    asm volatile("red.global.add.v4.f32 [%0], {%1,%2,%3,%4};"
                 :: "l"(p), "f"(v.x), "f"(v.y), "f"(v.z), "f"(v.w) : "memory");
}

// bias + relu + fp16-split c[8][4] (N=64) -> next-layer A fragments (4 k-tiles)
__device__ __forceinline__ void convert(const float c[8][4], const float* bias, int cc,
                                        uint32_t ah[4][4], uint32_t al[4][4]) {
    #pragma unroll
    for (int kk = 0; kk < 4; kk++) {
        #pragma unroll
        for (int h = 0; h < 2; h++) {
            int j = 2 * kk + h;
            float2 bb = *(const float2*)(bias + 8 * j + 2 * cc);
            float x0 = fmaxf(c[j][0] + bb.x, 0.f);
            float x1 = fmaxf(c[j][1] + bb.y, 0.f);
            float x2 = fmaxf(c[j][2] + bb.x, 0.f);
            float x3 = fmaxf(c[j][3] + bb.y, 0.f);
            ah[kk][2 * h]     = split2h(x0, x1, al[kk][2 * h]);
            ah[kk][2 * h + 1] = split2h(x2, x3, al[kk][2 * h + 1]);
        }
    }
}

// ---------------------------------------------------------------------------
// Prep: fragment-order fp16 weight images. One uint4 per thread.
// Fragment (mat, kt, jp, lane): n0 = 16*jp + (lane>>2), n1 = n0 + 8,
// k0 = kt*16 + 2*(lane&3).
// ---------------------------------------------------------------------------
__global__ void prep_weights(const float* __restrict__ eW1, const float* __restrict__ eW2,
                             const float* __restrict__ eW3, const float* __restrict__ nW1,
                             const float* __restrict__ nW2, const float* __restrict__ nW3) {
    int id = blockIdx.x * blockDim.x + threadIdx.x;
    if (id >= 2816) return;
    const float* W; int NJP, N; int rel;
    if      (id <  768) { W = eW1; NJP = 4; N = 64; rel = id; }
    else if (id < 1280) { W = eW2; NJP = 4; N = 64; rel = id - 768; }
    else if (id < 1536) { W = eW3; NJP = 2; N = 32; rel = id - 1280; }
    else if (id < 2048) { W = nW1; NJP = 4; N = 64; rel = id - 1536; }
    else if (id < 2560) { W = nW2; NJP = 4; N = 64; rel = id - 2048; }
    else                { W = nW3; NJP = 2; N = 32; rel = id - 2560; }
    int lane = rel & 31, fi = rel >> 5;
    int kt = fi / NJP, jp = fi % NJP;
    int n0 = 16 * jp + (lane >> 2);
    int n1 = n0 + 8;
    int k0 = kt * 16 + 2 * (lane & 3);
    uint4 o;
    o.x = packh(W[(size_t)k0 * N + n0],       W[(size_t)(k0 + 1) * N + n0]);
    o.y = packh(W[(size_t)(k0 + 8) * N + n0], W[(size_t)(k0 + 9) * N + n0]);
    o.z = packh(W[(size_t)k0 * N + n1],       W[(size_t)(k0 + 1) * N + n1]);
    o.w = packh(W[(size_t)(k0 + 8) * N + n1], W[(size_t)(k0 + 9) * N + n1]);
    g_wfrag[id] = o;
}

__global__ void zero_agg_kernel() {
    int i = blockIdx.x * blockDim.x + threadIdx.x;
    reinterpret_cast<float4*>(g_agg)[i] = make_float4(0.f, 0.f, 0.f, 0.f);
}

// ---------------------------------------------------------------------------
// Edge kernel: 128 threads = 4 warps, M=32 edges/warp (two m16 subtiles
// sharing every B-fragment load), EDGE_TILES tiles per CTA. occ 3.
// SMEM: 1536 uint4 weight frags (24576 B) + 160 bias + 4 warp bufs.
// ---------------------------------------------------------------------------
#define EDGE_WU4  1536
#define EDGE_SMEM (24576 + 640 + 4 * 2304)

__global__ void __launch_bounds__(128, 3)
edge_kernel(const float* __restrict__ nf, const float* __restrict__ ef,
            const int* __restrict__ src, const int* __restrict__ dst,
            const float* __restrict__ b1, const float* __restrict__ b2,
            const float* __restrict__ b3, float* __restrict__ out_ef) {
    extern __shared__ char sm[];
    const int tid = threadIdx.x, wid = tid >> 5, lane = tid & 31;

    uint4* wf = (uint4*)sm;
    for (int i = tid; i < EDGE_WU4; i += 128) wf[i] = g_wfrag[i];
    float* bias = (float*)(sm + 24576);
    if (tid < 64)       bias[tid] = b1[tid];
    else if (tid < 128) bias[tid] = b2[tid - 64];
    if (tid < 32)       bias[128 + tid] = b3[tid];
    float* buf = (float*)(sm + 25216) + wid * 576;
    __syncthreads();

    const int r = lane >> 2, cc = lane & 3;
    const uint4* F1 = wf;            // 6 kt x 4 jp x 32
    const uint4* F2 = wf + 768;      // 4 x 4 x 32
    const uint4* F3 = wf + 1280;     // 4 x 2 x 32

    for (int t = 0; t < EDGE_TILES; t++) {
        const int ew = (blockIdx.x * EDGE_TILES + t) * 128 + wid * 32;
        const int eA0 = ew + r,       eA1 = ew + 8 + r;
        const int eB0 = ew + 16 + r,  eB1 = ew + 24 + r;
        const int sA0 = src[eA0], sA1 = src[eA1], sB0 = src[eB0], sB1 = src[eB1];
        const int dA0 = dst[eA0], dA1 = dst[eA1], dB0 = dst[eB0], dB1 = dst[eB1];

        float cA[8][4], cB[8][4];
        #pragma unroll
        for (int j = 0; j < 8; j++)
            #pragma unroll
            for (int q = 0; q < 4; q++) { cA[j][q] = 0.f; cB[j][q] = 0.f; }

        // ---- L1: K = 96, A fragments gathered straight from global ----
        #pragma unroll
        for (int kt = 0; kt < 6; kt++) {
            const int cls = kt >> 1;
            const float *pA0, *pA1, *pB0, *pB1;
            if (cls == 0) {
                pA0 = nf + (size_t)sA0 * 32; pA1 = nf + (size_t)sA1 * 32;
                pB0 = nf + (size_t)sB0 * 32; pB1 = nf + (size_t)sB1 * 32;
            } else if (cls == 1) {
                pA0 = nf + (size_t)dA0 * 32; pA1 = nf + (size_t)dA1 * 32;
                pB0 = nf + (size_t)dB0 * 32; pB1 = nf + (size_t)dB1 * 32;
            } else {
                pA0 = ef + (size_t)eA0 * 32; pA1 = ef + (size_t)eA1 * 32;
                pB0 = ef + (size_t)eB0 * 32; pB1 = ef + (size_t)eB1 * 32;
            }
            const int o = ((kt & 1) << 4) + 2 * cc;
            float2 a00 = *(const float2*)(pA0 + o), a01 = *(const float2*)(pA0 + o + 8);
            float2 a10 = *(const float2*)(pA1 + o), a11 = *(const float2*)(pA1 + o + 8);
            float2 b00 = *(const float2*)(pB0 + o), b01 = *(const float2*)(pB0 + o + 8);
            float2 b10 = *(const float2*)(pB1 + o), b11 = *(const float2*)(pB1 + o + 8);
            uint32_t ahA[4], alA[4], ahB[4], alB[4];
            ahA[0] = split2h(a00.x, a00.y, alA[0]);
            ahA[1] = split2h(a10.x, a10.y, alA[1]);
            ahA[2] = split2h(a01.x, a01.y, alA[2]);
            ahA[3] = split2h(a11.x, a11.y, alA[3]);
            ahB[0] = split2h(b00.x, b00.y, alB[0]);
            ahB[1] = split2h(b10.x, b10.y, alB[1]);
            ahB[2] = split2h(b01.x, b01.y, alB[2]);
            ahB[3] = split2h(b11.x, b11.y, alB[3]);
            const uint4* fp = F1 + kt * 128 + lane;
            #pragma unroll
            for (int jj = 0; jj < 4; jj++)
                mma2x4(cA[2 * jj], cB[2 * jj], cA[2 * jj + 1], cB[2 * jj + 1],
                       ahA, alA, ahB, alB, fp + jj * 32);
        }

        uint32_t a2hA[4][4], a2lA[4][4], a2hB[4][4], a2lB[4][4];
        convert(cA, bias, cc, a2hA, a2lA);
        convert(cB, bias, cc, a2hB, a2lB);

        // ---- L2: K = 64 ----
        #pragma unroll
        for (int j = 0; j < 8; j++)
            #pragma unroll
            for (int q = 0; q < 4; q++) { cA[j][q] = 0.f; cB[j][q] = 0.f; }
        #pragma unroll
        for (int kt = 0; kt < 4; kt++) {
            const uint4* fp = F2 + kt * 128 + lane;
            #pragma unroll
            for (int jj = 0; jj < 4; jj++)
                mma2x4(cA[2 * jj], cB[2 * jj], cA[2 * jj + 1], cB[2 * jj + 1],
                       a2hA[kt], a2lA[kt], a2hB[kt], a2lB[kt], fp + jj * 32);
        }

        convert(cA, bias + 64, cc, a2hA, a2lA);   // reuse as a3
        convert(cB, bias + 64, cc, a2hB, a2lB);

        // ---- L3: K = 64, N = 32 (reuse cA/cB rows 0..3) ----
        #pragma unroll
        for (int j = 0; j < 4; j++)
            #pragma unroll
            for (int q = 0; q < 4; q++) { cA[j][q] = 0.f; cB[j][q] = 0.f; }
        #pragma unroll
        for (int kt = 0; kt < 4; kt++) {
            const uint4* fp = F3 + kt * 64 + lane;
            #pragma unroll
            for (int jj = 0; jj < 2; jj++)
                mma2x4(cA[2 * jj], cB[2 * jj], cA[2 * jj + 1], cB[2 * jj + 1],
                       a2hA[kt], a2lA[kt], a2hB[kt], a2lB[kt], fp + jj * 32);
        }

        // ---- epilogue, half A then half B through the 16-row warp buf ----
        #pragma unroll
        for (int half = 0; half < 2; half++) {
            #pragma unroll
            for (int j = 0; j < 4; j++) {
                float2 bb = *(const float2*)(bias + 128 + 8 * j + 2 * cc);
                int col = 8 * j + 2 * cc;
                const float* cj = half ? cB[j] : cA[j];
                buf[r * 36 + col]           = fmaxf(cj[0] + bb.x, 0.f);
                buf[r * 36 + col + 1]       = fmaxf(cj[1] + bb.y, 0.f);
                buf[(r + 8) * 36 + col]     = fmaxf(cj[2] + bb.x, 0.f);
                buf[(r + 8) * 36 + col + 1] = fmaxf(cj[3] + bb.y, 0.f);
            }
            __syncwarp();
            {
                const int row = lane >> 1, hh = lane & 1;
                const int e_row = ew + half * 16 + row;
                const int d = dst[e_row];
                const float* bp = buf + row * 36 + hh * 16;
                float4 v0 = *(const float4*)(bp);
                float4 v1 = *(const float4*)(bp + 4);
                float4 v2 = *(const float4*)(bp + 8);
                float4 v3 = *(const float4*)(bp + 12);
                float4* op = (float4*)(out_ef + (size_t)e_row * 32 + hh * 16);
                op[0] = v0; op[1] = v1; op[2] = v2; op[3] = v3;
                float* ap = g_agg + (size_t)d * 32 + hh * 16;
                red4(ap, v0); red4(ap + 4, v1); red4(ap + 8, v2); red4(ap + 12, v3);
            }
            __syncwarp();
        }
    }
}

// ---------------------------------------------------------------------------
// Node kernel: 256 threads, NODE_TILES x 128 nodes per CTA.
// ---------------------------------------------------------------------------
#define NODE_WU4  1280
#define NODE_SMEM (20480 + 640 + 8 * 2304)

__global__ void __launch_bounds__(256, 2)
node_kernel(const float* __restrict__ nf,
            const float* __restrict__ b1, const float* __restrict__ b2,
            const float* __restrict__ b3, float* __restrict__ out_nf) {
    extern __shared__ char sm[];
    const int tid = threadIdx.x, wid = tid >> 5, lane = tid & 31;

    uint4* wf = (uint4*)sm;
    for (int i = tid; i < NODE_WU4; i += 256) wf[i] = g_wfrag[1536 + i];
    float* bias = (float*)(sm + 20480);
    if (tid < 64)       bias[tid] = b1[tid];
    else if (tid < 128) bias[tid] = b2[tid - 64];
    else if (tid < 160) bias[tid] = b3[tid - 128];
    float* buf = (float*)(sm + 21120) + wid * 576;
    __syncthreads();

    const int r = lane >> 2, cc = lane & 3;
    const uint4* F1 = wf;            // 4 kt x 4 jp x 32
    const uint4* F2 = wf + 512;
    const uint4* F3 = wf + 1024;     // 4 kt x 2 jp x 32

    for (int t = 0; t < NODE_TILES; t++) {
        const int n0w = (blockIdx.x * NODE_TILES + t) * 128 + wid * 16;
        if (n0w >= N_NODES) break;
        const int ra = min(n0w + r, N_NODES - 1);
        const int rb = min(n0w + r + 8, N_NODES - 1);
        const float* PA[2] = { nf + (size_t)ra * 32, g_agg + (size_t)ra * 32 };
        const float* PB[2] = { nf + (size_t)rb * 32, g_agg + (size_t)rb * 32 };

        float c[8][4];
        #pragma unroll
        for (int j = 0; j < 8; j++) { c[j][0] = c[j][1] = c[j][2] = c[j][3] = 0.f; }

        #pragma unroll
        for (int kt = 0; kt < 4; kt++) {
            const float* pa = PA[kt >> 1];
            const float* pb = PB[kt >> 1];
            const int o = ((kt & 1) << 4) + 2 * cc;
            float2 va0 = *(const float2*)(pa + o), va1 = *(const float2*)(pa + o + 8);
            float2 vb0 = *(const float2*)(pb + o), vb1 = *(const float2*)(pb + o + 8);
            uint32_t ah[4], al[4];
            ah[0] = split2h(va0.x, va0.y, al[0]);
            ah[1] = split2h(vb0.x, vb0.y, al[1]);
            ah[2] = split2h(va1.x, va1.y, al[2]);
            ah[3] = split2h(vb1.x, vb1.y, al[3]);
            const uint4* fp = F1 + kt * 128 + lane;
            #pragma unroll
            for (int jp = 0; jp < 4; jp++)
                mma2x2(c[2 * jp], c[2 * jp + 1], ah, al, fp + jp * 32);
        }

        uint32_t a2h[4][4], a2l[4][4];
        convert(c, bias, cc, a2h, a2l);

        #pragma unroll
        for (int j = 0; j < 8; j++) { c[j][0] = c[j][1] = c[j][2] = c[j][3] = 0.f; }
        #pragma unroll
        for (int kt = 0; kt < 4; kt++) {
            const uint4* fp = F2 + kt * 128 + lane;
            #pragma unroll
            for (int jp = 0; jp < 4; jp++)
                mma2x2(c[2 * jp], c[2 * jp + 1], a2h[kt], a2l[kt], fp + jp * 32);
        }

        convert(c, bias + 64, cc, a2h, a2l);   // reuse as a3

        float c3[4][4];
        #pragma unroll
        for (int j = 0; j < 4; j++) { c3[j][0] = c3[j][1] = c3[j][2] = c3[j][3] = 0.f; }
        #pragma unroll
        for (int kt = 0; kt < 4; kt++) {
            const uint4* fp = F3 + kt * 64 + lane;
            #pragma unroll
            for (int jp = 0; jp < 2; jp++)
                mma2x2(c3[2 * jp], c3[2 * jp + 1], a2h[kt], a2l[kt], fp + jp * 32);
        }

        #pragma unroll
        for (int j = 0; j < 4; j++) {
            float2 bb = *(const float2*)(bias + 128 + 8 * j + 2 * cc);
            int col = 8 * j + 2 * cc;
            buf[r * 36 + col]           = fmaxf(c3[j][0] + bb.x, 0.f);
            buf[r * 36 + col + 1]       = fmaxf(c3[j][1] + bb.y, 0.f);
            buf[(r + 8) * 36 + col]     = fmaxf(c3[j][2] + bb.x, 0.f);
            buf[(r + 8) * 36 + col + 1] = fmaxf(c3[j][3] + bb.y, 0.f);
        }
        __syncwarp();
        {
            const int row = lane >> 1, half = lane & 1;
            const int n_row = n0w + row;
            if (n_row < N_NODES) {
                const float* bp = buf + row * 36 + half * 16;
                float4* op = (float4*)(out_nf + (size_t)n_row * 32 + half * 16);
                op[0] = *(const float4*)(bp);
                op[1] = *(const float4*)(bp + 4);
                op[2] = *(const float4*)(bp + 8);
                op[3] = *(const float4*)(bp + 12);
            }
        }
        __syncwarp();
    }
}

// ---------------------------------------------------------------------------
extern "C" void kernel_launch(void* const* d_in, const int* in_sizes, int n_in,
                              void* d_out, int out_size) {
    const float* nf  = (const float*)d_in[0];
    const float* ef  = (const float*)d_in[1];
    const int*   src = (const int*)d_in[2];
    const int*   dst = (const int*)d_in[3];
    const float* eW1 = (const float*)d_in[4];
    const float* eb1 = (const float*)d_in[5];
    const float* eW2 = (const float*)d_in[6];
    const float* eb2 = (const float*)d_in[7];
    const float* eW3 = (const float*)d_in[8];
    const float* eb3 = (const float*)d_in[9];
    const float* nW1 = (const float*)d_in[10];
    const float* nb1 = (const float*)d_in[11];
    const float* nW2 = (const float*)d_in[12];
    const float* nb2 = (const float*)d_in[13];
    const float* nW3 = (const float*)d_in[14];
    const float* nb3 = (const float*)d_in[15];

    float* out_nf = (float*)d_out;
    float* out_ef = out_nf + (size_t)N_NODES * 32;

    cudaFuncSetAttribute(edge_kernel, cudaFuncAttributeMaxDynamicSharedMemorySize, EDGE_SMEM);
    cudaFuncSetAttribute(node_kernel, cudaFuncAttributeMaxDynamicSharedMemorySize, NODE_SMEM);

    prep_weights<<<22, 128>>>(eW1, eW2, eW3, nW1, nW2, nW3);
    zero_agg_kernel<<<3125, 256>>>();
    edge_kernel<<<N_EDGES / (128 * EDGE_TILES), 128, EDGE_SMEM>>>(
        nf, ef, src, dst, eb1, eb2, eb3, out_ef);
    node_kernel<<<(N_NODES + 255) / 256, 256, NODE_SMEM>>>(
        nf, nb1, nb2, nb3, out_nf);
}